// round 14
// baseline (speedup 1.0000x reference)
#include <cuda_runtime.h>
#include <cstdint>

#define HD 512
#define BB 32
#define SN 400
#define TT 400
#define NBLK 128
#define TPB 512
#define NTHREADS (NBLK*TPB)
#define NWARP (NTHREADS/32)   // 2048

// ---------------- persistent device scratch (no allocations) ----------------
__device__ float g_Penc[SN*BB*HD];      // 26 MB: fc_W @ enc  (time-invariant)
__device__ float g_Ph[BB*HD];           // fc_W @ h
__device__ float g_gh[BB*3*HD];         // Whh @ h
__device__ float g_gix[BB*3*HD];        // x @ Wih[:, :H]^T
__device__ float g_e[SN*BB];            // attention logits [s][b]
__device__ float g_ctx[BB*HD];          // context
__device__ float g_hst[2][BB*HD];       // hidden double buffer

// monotonic grid barrier state (zero-initialized; never reset -> replay safe)
__device__ unsigned long long g_arrive;
__device__ unsigned long long g_rel;

__device__ __forceinline__ float tanha(float x) {
    float y;
    asm("tanh.approx.f32 %0, %1;" : "=f"(y) : "f"(x));
    return y;
}

__device__ __forceinline__ float warpsum(float v) {
#pragma unroll
    for (int o = 16; o > 0; o >>= 1) v += __shfl_xor_sync(0xffffffffu, v, o);
    return v;
}

// Grid-wide barrier via monotonic counters. Works across graph replays.
__device__ __forceinline__ void gridbar() {
    __syncthreads();
    if (threadIdx.x == 0) {
        __threadfence();
        unsigned long long v = atomicAdd(&g_arrive, 1ULL) + 1ULL;
        unsigned long long bar = (v - 1ULL) / (unsigned long long)NBLK;
        if (v == (bar + 1ULL) * (unsigned long long)NBLK) {
            atomicExch(&g_rel, bar + 1ULL);
        } else {
            while (*((volatile unsigned long long*)&g_rel) < bar + 1ULL) { }
        }
        __threadfence();
    }
    __syncthreads();
}

// warp dot of two 512-float vectors (float4, shuffle reduce)
__device__ __forceinline__ float wdot512(const float* __restrict__ v,
                                         const float* __restrict__ w, int lane) {
    const float4* v4 = (const float4*)v;
    const float4* w4 = (const float4*)w;
    float acc = 0.f;
#pragma unroll
    for (int i = 0; i < 4; ++i) {
        float4 a = v4[lane + (i << 5)];
        float4 b = w4[lane + (i << 5)];
        acc = fmaf(a.x, b.x, fmaf(a.y, b.y, fmaf(a.z, b.z, fmaf(a.w, b.w, acc))));
    }
    return warpsum(acc);
}

__global__ void __launch_bounds__(TPB)
decoder_kernel(const float* __restrict__ dec,   // (T,B,H)
               const float* __restrict__ enc,   // (S,B,H)
               const float* __restrict__ fcW,   // (H,H)
               const float* __restrict__ attw,  // (H)
               const float* __restrict__ Wih,   // (3H,2H)
               const float* __restrict__ Whh,   // (3H,H)
               const float* __restrict__ specW, // (H,H)
               const float* __restrict__ specb, // (H)
               const float* __restrict__ gateW, // (H)
               const float* __restrict__ gateb, // (1)
               float* __restrict__ out)         // B*T*H mel + B*T gate
{
    const int tid  = threadIdx.x;
    const int bid  = blockIdx.x;
    const int gtid = bid * TPB + tid;
    const int wid  = gtid >> 5;
    const int lane = tid & 31;

    __shared__ float As[16][132];
    __shared__ float Bs[16][68];
    __shared__ float s_alpha[SN];
    __shared__ float s_red[TPB];

    // -------- zero init of recurrent buffers (h0 = 0, x0 = 0) --------
    for (int i = gtid; i < BB*HD; i += NTHREADS) { g_Ph[i] = 0.f; g_hst[0][i] = 0.f; }
    for (int i = gtid; i < BB*3*HD; i += NTHREADS) { g_gh[i] = 0.f; g_gix[i] = 0.f; }

    // -------- Penc GEMM: Penc[m][e] = sum_k enc[m*H+k] * fcW[e*H+k] --------
    {
        const int tm = (tid >> 4) << 2;    // 0..124
        const int tn = (tid & 15) << 2;    // 0..60
        const int NT = (SN*BB/128) * (HD/64);   // 100*8 = 800 tiles
        for (int tile = bid; tile < NT; tile += NBLK) {
            const int m0 = (tile >> 3) * 128;
            const int n0 = (tile & 7) * 64;
            float acc[4][4];
#pragma unroll
            for (int i = 0; i < 4; ++i)
#pragma unroll
                for (int j = 0; j < 4; ++j) acc[i][j] = 0.f;

            for (int k0 = 0; k0 < HD; k0 += 16) {
                {   // load A tile 128x16 (transposed into [k][m])
                    int m = tid >> 2, kq = (tid & 3) << 2;
                    float4 v = *(const float4*)(enc + (size_t)(m0 + m) * HD + k0 + kq);
                    As[kq+0][m] = v.x; As[kq+1][m] = v.y; As[kq+2][m] = v.z; As[kq+3][m] = v.w;
                }
                if (tid < 256) {  // load B tile 64x16
                    int n = tid >> 2, kq = (tid & 3) << 2;
                    float4 v = *(const float4*)(fcW + (size_t)(n0 + n) * HD + k0 + kq);
                    Bs[kq+0][n] = v.x; Bs[kq+1][n] = v.y; Bs[kq+2][n] = v.z; Bs[kq+3][n] = v.w;
                }
                __syncthreads();
#pragma unroll
                for (int kk = 0; kk < 16; ++kk) {
                    float4 a = *(const float4*)&As[kk][tm];
                    float4 b = *(const float4*)&Bs[kk][tn];
                    float av[4] = {a.x, a.y, a.z, a.w};
                    float bv[4] = {b.x, b.y, b.z, b.w};
#pragma unroll
                    for (int i = 0; i < 4; ++i)
#pragma unroll
                        for (int j = 0; j < 4; ++j)
                            acc[i][j] = fmaf(av[i], bv[j], acc[i][j]);
                }
                __syncthreads();
            }
#pragma unroll
            for (int i = 0; i < 4; ++i)
#pragma unroll
                for (int j = 0; j < 4; ++j)
                    g_Penc[(size_t)(m0 + tm + i) * HD + n0 + tn + j] = acc[i][j];
        }
    }
    gridbar();

    int cur = 0;
    for (int t = 0; t < TT; ++t) {
        // -------- P2: logits e[s][b] = sum_e attw[e]*tanh(Ph[b,e]+Penc[s,b,e]) --------
        for (int p = wid; p < SN*BB; p += NWARP) {
            const int b = p & 31;
            const float4* pe = (const float4*)(g_Penc + (size_t)p * HD);
            const float4* ph = (const float4*)(g_Ph + b * HD);
            const float4* aw = (const float4*)attw;
            float acc = 0.f;
#pragma unroll
            for (int i = 0; i < 4; ++i) {
                int idx = lane + (i << 5);
                float4 p4 = pe[idx];
                float4 h4 = ph[idx];
                float4 w4 = aw[idx];
                acc = fmaf(tanha(p4.x + h4.x), w4.x, acc);
                acc = fmaf(tanha(p4.y + h4.y), w4.y, acc);
                acc = fmaf(tanha(p4.z + h4.z), w4.z, acc);
                acc = fmaf(tanha(p4.w + h4.w), w4.w, acc);
            }
            acc = warpsum(acc);
            if (lane == 0) g_e[p] = acc;
        }
        gridbar();

        // -------- P3: softmax over s (per b) + ctx[b,:] --------
        {
            const int b = bid & 31;
            const int h0 = (bid >> 5) << 7;   // 4 tiles of 128 h per b
            float v = (tid < SN) ? g_e[tid * BB + b] : -3.0e38f;
            s_red[tid] = v;
            __syncthreads();
            for (int o = TPB >> 1; o > 0; o >>= 1) {
                if (tid < o) s_red[tid] = fmaxf(s_red[tid], s_red[tid + o]);
                __syncthreads();
            }
            float mx = s_red[0];
            __syncthreads();
            float ex = (tid < SN) ? __expf(v - mx) : 0.f;
            if (tid < SN) s_alpha[tid] = ex;
            s_red[tid] = ex;
            __syncthreads();
            for (int o = TPB >> 1; o > 0; o >>= 1) {
                if (tid < o) s_red[tid] += s_red[tid + o];
                __syncthreads();
            }
            float inv = 1.f / s_red[0];
            __syncthreads();
            const int hh = h0 + (tid & 127);
            const int sp = tid >> 7;           // 4-way s split
            float acc = 0.f;
#pragma unroll 4
            for (int s = sp; s < SN; s += 4)
                acc = fmaf(s_alpha[s], enc[((size_t)s * BB + b) * HD + hh], acc);
            s_red[tid] = acc;
            __syncthreads();
            if (sp == 0)
                g_ctx[b * HD + hh] =
                    (s_red[tid] + s_red[tid + 128] + s_red[tid + 256] + s_red[tid + 384]) * inv;
        }
        gridbar();

        // -------- P4: GRU update -> h2 --------
        {
            const int nxt = cur ^ 1;
            for (int o = wid; o < BB*HD; o += NWARP) {
                const int b = o & 31;
                const int j = o >> 5;
                const float4* cx = (const float4*)(g_ctx + b * HD);
                const float4* wr = (const float4*)(Wih + (size_t)j * 1024 + 512);
                const float4* wz = (const float4*)(Wih + (size_t)(512 + j) * 1024 + 512);
                const float4* wn = (const float4*)(Wih + (size_t)(1024 + j) * 1024 + 512);
                float ar = 0.f, az = 0.f, an = 0.f;
#pragma unroll
                for (int i = 0; i < 4; ++i) {
                    int idx = lane + (i << 5);
                    float4 c4 = cx[idx];
                    float4 r4 = wr[idx], z4 = wz[idx], n4 = wn[idx];
                    ar = fmaf(c4.x, r4.x, fmaf(c4.y, r4.y, fmaf(c4.z, r4.z, fmaf(c4.w, r4.w, ar))));
                    az = fmaf(c4.x, z4.x, fmaf(c4.y, z4.y, fmaf(c4.z, z4.z, fmaf(c4.w, z4.w, az))));
                    an = fmaf(c4.x, n4.x, fmaf(c4.y, n4.y, fmaf(c4.z, n4.z, fmaf(c4.w, n4.w, an))));
                }
                ar = warpsum(ar); az = warpsum(az); an = warpsum(an);
                if (lane == 0) {
                    const float* gx = g_gix + b * 1536;
                    const float* gg = g_gh + b * 1536;
                    float ir  = gx[j]        + ar + gg[j];
                    float iz  = gx[512 + j]  + az + gg[512 + j];
                    float inn = gx[1024 + j] + an;
                    float hn  = gg[1024 + j];
                    float r = 1.f / (1.f + __expf(-ir));
                    float z = 1.f / (1.f + __expf(-iz));
                    float n = tanhf(fmaf(r, hn, inn));
                    float hp = g_hst[cur][b * HD + j];
                    g_hst[nxt][b * HD + j] = fmaf(z, hp - n, n);  // (1-z)*n + z*hp
                }
            }
        }
        gridbar();

        // -------- P1': outputs (mel, gate) + next-step Ph, gh, gix --------
        {
            const int nxt = cur ^ 1;
            const float* h2 = g_hst[nxt];
            // mel
            for (int u = wid; u < BB*HD; u += NWARP) {
                int b = u & 31, e = u >> 5;
                float d = wdot512(h2 + b * HD, specW + (size_t)e * HD, lane);
                if (lane == 0)
                    out[(size_t)b * TT * HD + (size_t)t * HD + e] = d + specb[e];
            }
            // Ph'
            for (int u = wid; u < BB*HD; u += NWARP) {
                int b = u & 31, e = u >> 5;
                float d = wdot512(h2 + b * HD, fcW + (size_t)e * HD, lane);
                if (lane == 0) g_Ph[b * HD + e] = d;
            }
            // gh'
            for (int u = wid; u < BB*3*HD; u += NWARP) {
                int b = u & 31, r = u >> 5;
                float d = wdot512(h2 + b * HD, Whh + (size_t)r * HD, lane);
                if (lane == 0) g_gh[b * 1536 + r] = d;
            }
            // gix' from x_{t+1} = dec[t]
            if (t + 1 < TT) {
                const float* x = dec + (size_t)t * BB * HD;
                for (int u = wid; u < BB*3*HD; u += NWARP) {
                    int b = u & 31, r = u >> 5;
                    float d = wdot512(x + b * HD, Wih + (size_t)r * 1024, lane);
                    if (lane == 0) g_gix[b * 1536 + r] = d;
                }
            }
            // gate
            for (int u = wid; u < BB; u += NWARP) {
                float d = wdot512(h2 + u * HD, gateW, lane);
                if (lane == 0)
                    out[(size_t)BB * TT * HD + (size_t)u * TT + t] = d + gateb[0];
            }
        }
        gridbar();

        cur ^= 1;
    }
}

extern "C" void kernel_launch(void* const* d_in, const int* in_sizes, int n_in,
                              void* d_out, int out_size) {
    (void)in_sizes; (void)n_in; (void)out_size;
    decoder_kernel<<<NBLK, TPB>>>(
        (const float*)d_in[0],   // decoder_inputs
        (const float*)d_in[1],   // alignment_inputs
        (const float*)d_in[2],   // fc_W
        (const float*)d_in[3],   // att_w
        (const float*)d_in[4],   // Wih
        (const float*)d_in[5],   // Whh
        (const float*)d_in[6],   // spec_W
        (const float*)d_in[7],   // spec_b
        (const float*)d_in[8],   // gate_W
        (const float*)d_in[9],   // gate_b
        (float*)d_out);
}

// round 15
// speedup vs baseline: 1.2186x; 1.2186x over previous
#include <cuda_runtime.h>
#include <cstdint>

#define HD 512
#define BB 32
#define SN 400
#define TT 400
#define NBLK 128
#define TPB 512
#define NTHREADS (NBLK*TPB)
#define NWARP (NTHREADS/32)   // 2048

// ---------------- persistent device scratch (no allocations) ----------------
__device__ float g_Penc[SN*BB*HD];      // 26 MB: fc_W @ enc  (time-invariant)
__device__ float g_Ph[BB*HD];           // fc_W @ h
__device__ float g_gh[BB*3*HD];         // Whh @ h
__device__ float g_gix[2][BB*3*HD];     // x @ Wih_x^T (double buffered)
__device__ float g_e[SN*BB];            // attention logits [s][b]
__device__ float g_ctx[BB*HD];          // context
__device__ float g_hst[2][BB*HD];       // hidden double buffer

// monotonic grid barrier state (zero-initialized; never reset -> replay safe)
__device__ unsigned long long g_arrive;
__device__ unsigned long long g_rel;

__device__ __forceinline__ float tanha(float x) {
    float y;
    asm("tanh.approx.f32 %0, %1;" : "=f"(y) : "f"(x));
    return y;
}

__device__ __forceinline__ float warpsum(float v) {
#pragma unroll
    for (int o = 16; o > 0; o >>= 1) v += __shfl_xor_sync(0xffffffffu, v, o);
    return v;
}

__device__ __forceinline__ float dot4(float4 a, float4 b, float acc) {
    return fmaf(a.x, b.x, fmaf(a.y, b.y, fmaf(a.z, b.z, fmaf(a.w, b.w, acc))));
}

// Grid-wide barrier via monotonic counters. Works across graph replays.
__device__ __forceinline__ void gridbar() {
    __syncthreads();
    if (threadIdx.x == 0) {
        __threadfence();
        unsigned long long v = atomicAdd(&g_arrive, 1ULL) + 1ULL;
        unsigned long long bar = (v - 1ULL) / (unsigned long long)NBLK;
        if (v == (bar + 1ULL) * (unsigned long long)NBLK) {
            atomicExch(&g_rel, bar + 1ULL);
        } else {
            while (*((volatile unsigned long long*)&g_rel) < bar + 1ULL) { }
        }
        __threadfence();
    }
    __syncthreads();
}

// warp dot of two 512-float vectors (float4, shuffle reduce)
__device__ __forceinline__ float wdot512(const float* __restrict__ v,
                                         const float* __restrict__ w, int lane) {
    const float4* v4 = (const float4*)v;
    const float4* w4 = (const float4*)w;
    float acc = 0.f;
#pragma unroll
    for (int i = 0; i < 4; ++i)
        acc = dot4(v4[lane + (i << 5)], w4[lane + (i << 5)], acc);
    return warpsum(acc);
}

__global__ void __launch_bounds__(TPB)
decoder_kernel(const float* __restrict__ dec,   // (T,B,H)
               const float* __restrict__ enc,   // (S,B,H)
               const float* __restrict__ fcW,   // (H,H)
               const float* __restrict__ attw,  // (H)
               const float* __restrict__ Wih,   // (3H,2H)
               const float* __restrict__ Whh,   // (3H,H)
               const float* __restrict__ specW, // (H,H)
               const float* __restrict__ specb, // (H)
               const float* __restrict__ gateW, // (H)
               const float* __restrict__ gateb, // (1)
               float* __restrict__ out)         // B*T*H mel + B*T gate
{
    const int tid  = threadIdx.x;
    const int bid  = blockIdx.x;
    const int gtid = bid * TPB + tid;
    const int wl   = tid >> 5;          // warp in block (0..15)
    const int wid  = gtid >> 5;         // global warp
    const int lane = tid & 31;

    __shared__ float As[16][132];
    __shared__ float Bs[16][68];
    __shared__ float s_alpha[SN];
    __shared__ float s_red[TPB];

    // -------- zero init of recurrent buffers (h0 = 0, x0 = 0) --------
    for (int i = gtid; i < BB*HD; i += NTHREADS) { g_Ph[i] = 0.f; g_hst[0][i] = 0.f; }
    for (int i = gtid; i < BB*3*HD; i += NTHREADS) { g_gh[i] = 0.f; g_gix[0][i] = 0.f; }

    // -------- Penc GEMM: Penc[m][e] = sum_k enc[m*H+k] * fcW[e*H+k] --------
    {
        const int tm = (tid >> 4) << 2;
        const int tn = (tid & 15) << 2;
        const int NT = (SN*BB/128) * (HD/64);   // 800 tiles
        for (int tile = bid; tile < NT; tile += NBLK) {
            const int m0 = (tile >> 3) * 128;
            const int n0 = (tile & 7) * 64;
            float acc[4][4];
#pragma unroll
            for (int i = 0; i < 4; ++i)
#pragma unroll
                for (int j = 0; j < 4; ++j) acc[i][j] = 0.f;

            for (int k0 = 0; k0 < HD; k0 += 16) {
                {
                    int m = tid >> 2, kq = (tid & 3) << 2;
                    float4 v = *(const float4*)(enc + (size_t)(m0 + m) * HD + k0 + kq);
                    As[kq+0][m] = v.x; As[kq+1][m] = v.y; As[kq+2][m] = v.z; As[kq+3][m] = v.w;
                }
                if (tid < 256) {
                    int n = tid >> 2, kq = (tid & 3) << 2;
                    float4 v = *(const float4*)(fcW + (size_t)(n0 + n) * HD + k0 + kq);
                    Bs[kq+0][n] = v.x; Bs[kq+1][n] = v.y; Bs[kq+2][n] = v.z; Bs[kq+3][n] = v.w;
                }
                __syncthreads();
#pragma unroll
                for (int kk = 0; kk < 16; ++kk) {
                    float4 a = *(const float4*)&As[kk][tm];
                    float4 b = *(const float4*)&Bs[kk][tn];
                    float av[4] = {a.x, a.y, a.z, a.w};
                    float bv[4] = {b.x, b.y, b.z, b.w};
#pragma unroll
                    for (int i = 0; i < 4; ++i)
#pragma unroll
                        for (int j = 0; j < 4; ++j)
                            acc[i][j] = fmaf(av[i], bv[j], acc[i][j]);
                }
                __syncthreads();
            }
#pragma unroll
            for (int i = 0; i < 4; ++i)
#pragma unroll
                for (int j = 0; j < 4; ++j)
                    g_Penc[(size_t)(m0 + tm + i) * HD + n0 + tn + j] = acc[i][j];
        }
    }
    gridbar();

    int cur = 0;
    for (int t = 0; t < TT; ++t) {
        // ======== P2: logits e[s][b] = sum_e attw[e]*tanh(Ph[b,e]+Penc[s,b,e]) ========
        for (int p = wid; p < SN*BB; p += NWARP) {
            const int b = p & 31;
            const float4* pe = (const float4*)(g_Penc + (size_t)p * HD);
            const float4* ph = (const float4*)(g_Ph + b * HD);
            const float4* aw = (const float4*)attw;
            float acc = 0.f;
#pragma unroll
            for (int i = 0; i < 4; ++i) {
                int idx = lane + (i << 5);
                float4 p4 = pe[idx];
                float4 h4 = ph[idx];
                float4 w4 = aw[idx];
                acc = fmaf(tanha(p4.x + h4.x), w4.x, acc);
                acc = fmaf(tanha(p4.y + h4.y), w4.y, acc);
                acc = fmaf(tanha(p4.z + h4.z), w4.z, acc);
                acc = fmaf(tanha(p4.w + h4.w), w4.w, acc);
            }
            acc = warpsum(acc);
            if (lane == 0) g_e[p] = acc;
        }
        gridbar();

        // ======== P3: softmax over s (per b) + ctx[b,:] ========
        {
            const int b = bid & 31;
            const int h0 = (bid >> 5) << 7;
            float v = (tid < SN) ? g_e[tid * BB + b] : -3.0e38f;
            s_red[tid] = v;
            __syncthreads();
            for (int o = TPB >> 1; o > 0; o >>= 1) {
                if (tid < o) s_red[tid] = fmaxf(s_red[tid], s_red[tid + o]);
                __syncthreads();
            }
            float mx = s_red[0];
            __syncthreads();
            float ex = (tid < SN) ? __expf(v - mx) : 0.f;
            if (tid < SN) s_alpha[tid] = ex;
            s_red[tid] = ex;
            __syncthreads();
            for (int o = TPB >> 1; o > 0; o >>= 1) {
                if (tid < o) s_red[tid] += s_red[tid + o];
                __syncthreads();
            }
            float inv = 1.f / s_red[0];
            __syncthreads();
            const int hh = h0 + (tid & 127);
            const int sp = tid >> 7;
            float acc = 0.f;
#pragma unroll 4
            for (int s = sp; s < SN; s += 4)
                acc = fmaf(s_alpha[s], enc[((size_t)s * BB + b) * HD + hh], acc);
            s_red[tid] = acc;
            __syncthreads();
            if (sp == 0)
                g_ctx[b * HD + hh] =
                    (s_red[tid] + s_red[tid + 128] + s_red[tid + 256] + s_red[tid + 384]) * inv;
        }
        gridbar();

        // ======== P4: GRU update (weight-stationary) + gix for next step ========
        {
            const int nxt = cur ^ 1;
            const int task = bid * 14 + wl;
            if (wl < 14) {
                if (task < 1024) {
                    // GRU column j for 16 batch elems: ar/az/an via Wih ctx-half, combine -> h2
                    const int j  = task >> 1;
                    const int b0 = (task & 1) << 4;
                    const float4* WR = (const float4*)(Wih + (size_t)j * 1024 + 512);
                    const float4* WZ = (const float4*)(Wih + (size_t)(512 + j) * 1024 + 512);
                    const float4* WN = (const float4*)(Wih + (size_t)(1024 + j) * 1024 + 512);
                    float4 wr[4], wz[4], wn[4];
#pragma unroll
                    for (int i = 0; i < 4; ++i) {
                        int idx = lane + (i << 5);
                        wr[i] = WR[idx]; wz[i] = WZ[idx]; wn[i] = WN[idx];
                    }
                    const float* gx = g_gix[cur];
                    const float* hc = g_hst[cur];
                    for (int b = b0; b < b0 + 16; ++b) {
                        const float4* c4 = (const float4*)(g_ctx + b * HD);
                        float ar = 0.f, az = 0.f, an = 0.f;
#pragma unroll
                        for (int i = 0; i < 4; ++i) {
                            float4 c = c4[lane + (i << 5)];
                            ar = dot4(c, wr[i], ar);
                            az = dot4(c, wz[i], az);
                            an = dot4(c, wn[i], an);
                        }
                        ar = warpsum(ar); az = warpsum(az); an = warpsum(an);
                        const float* gxb = gx + b * 1536;
                        const float* ggb = g_gh + b * 1536;
                        float ir  = gxb[j]        + ar + ggb[j];
                        float iz  = gxb[512 + j]  + az + ggb[512 + j];
                        float inn = gxb[1024 + j] + an;
                        float hn  = ggb[1024 + j];
                        float r = 1.f / (1.f + __expf(-ir));
                        float z = 1.f / (1.f + __expf(-iz));
                        float n = tanhf(fmaf(r, hn, inn));
                        float hp = hc[b * HD + j];
                        if (lane == 0)
                            g_hst[nxt][b * HD + j] = fmaf(z, hp - n, n);
                    }
                } else {
                    // gix for next step: rows 4*rg..4*rg+3 of Wih x-half vs x_{t+1}=dec[t]
                    const int t2 = task - 1024;         // 0..767
                    const int rg = t2 >> 1;
                    const int b0 = (t2 & 1) << 4;
                    const int r0 = rg << 2;
                    float4 w[4][4];
#pragma unroll
                    for (int r = 0; r < 4; ++r) {
                        const float4* Wp = (const float4*)(Wih + (size_t)(r0 + r) * 1024);
#pragma unroll
                        for (int i = 0; i < 4; ++i) w[r][i] = Wp[lane + (i << 5)];
                    }
                    const float* x = dec + (size_t)t * BB * HD;
                    float* gxo = g_gix[nxt];
                    for (int b = b0; b < b0 + 16; ++b) {
                        const float4* xb = (const float4*)(x + b * HD);
                        float4 h4[4];
#pragma unroll
                        for (int i = 0; i < 4; ++i) h4[i] = xb[lane + (i << 5)];
                        float acc[4] = {0.f, 0.f, 0.f, 0.f};
#pragma unroll
                        for (int r = 0; r < 4; ++r)
#pragma unroll
                            for (int i = 0; i < 4; ++i)
                                acc[r] = dot4(h4[i], w[r][i], acc[r]);
#pragma unroll
                        for (int r = 0; r < 4; ++r) acc[r] = warpsum(acc[r]);
                        if (lane == 0) {
#pragma unroll
                            for (int r = 0; r < 4; ++r)
                                gxo[b * 1536 + r0 + r] = acc[r];
                        }
                    }
                }
            }
        }
        gridbar();

        // ======== Epilogue: mel, gate outputs + next-step Ph, gh (weight-stationary) ========
        {
            const int nxt = cur ^ 1;
            const float* h2 = g_hst[nxt];
            const int task = bid * 10 + wl;
            if (wl < 10) {
                const int g  = task >> 1;        // 0..639
                const int b0 = (task & 1) << 4;
                const float* W;
                int mode, r0;
                if (g < 128)      { r0 = g << 2;          W = specW + (size_t)r0 * HD; mode = 0; }
                else if (g < 256) { r0 = (g - 128) << 2;  W = fcW   + (size_t)r0 * HD; mode = 1; }
                else              { r0 = (g - 256) << 2;  W = Whh   + (size_t)r0 * HD; mode = 2; }
                float4 w[4][4];
#pragma unroll
                for (int r = 0; r < 4; ++r) {
                    const float4* Wp = (const float4*)(W + (size_t)r * HD);
#pragma unroll
                    for (int i = 0; i < 4; ++i) w[r][i] = Wp[lane + (i << 5)];
                }
                for (int b = b0; b < b0 + 16; ++b) {
                    const float4* hb = (const float4*)(h2 + b * HD);
                    float4 h4[4];
#pragma unroll
                    for (int i = 0; i < 4; ++i) h4[i] = hb[lane + (i << 5)];
                    float acc[4] = {0.f, 0.f, 0.f, 0.f};
#pragma unroll
                    for (int r = 0; r < 4; ++r)
#pragma unroll
                        for (int i = 0; i < 4; ++i)
                            acc[r] = dot4(h4[i], w[r][i], acc[r]);
#pragma unroll
                    for (int r = 0; r < 4; ++r) acc[r] = warpsum(acc[r]);
                    if (lane == 0) {
                        if (mode == 0) {
#pragma unroll
                            for (int r = 0; r < 4; ++r)
                                out[(size_t)b * TT * HD + (size_t)t * HD + r0 + r] =
                                    acc[r] + specb[r0 + r];
                        } else if (mode == 1) {
#pragma unroll
                            for (int r = 0; r < 4; ++r)
                                g_Ph[b * HD + r0 + r] = acc[r];
                        } else {
#pragma unroll
                            for (int r = 0; r < 4; ++r)
                                g_gh[b * 1536 + r0 + r] = acc[r];
                        }
                    }
                }
            } else if (bid == 0 && (wl == 10 || wl == 11)) {
                const int b0 = (wl - 10) << 4;
                for (int b = b0; b < b0 + 16; ++b) {
                    float d = wdot512(h2 + b * HD, gateW, lane);
                    if (lane == 0)
                        out[(size_t)BB * TT * HD + (size_t)b * TT + t] = d + gateb[0];
                }
            }
        }
        gridbar();

        cur ^= 1;
    }
}

extern "C" void kernel_launch(void* const* d_in, const int* in_sizes, int n_in,
                              void* d_out, int out_size) {
    (void)in_sizes; (void)n_in; (void)out_size;
    decoder_kernel<<<NBLK, TPB>>>(
        (const float*)d_in[0],   // decoder_inputs
        (const float*)d_in[1],   // alignment_inputs
        (const float*)d_in[2],   // fc_W
        (const float*)d_in[3],   // att_w
        (const float*)d_in[4],   // Wih
        (const float*)d_in[5],   // Whh
        (const float*)d_in[6],   // spec_W
        (const float*)d_in[7],   // spec_b
        (const float*)d_in[8],   // gate_W
        (const float*)d_in[9],   // gate_b
        (float*)d_out);
}